// round 6
// baseline (speedup 1.0000x reference)
#include <cuda_runtime.h>

// Problem dims
#define SQ    2048
#define BATCH 64
#define IDIM  256
#define HDIM  512
#define EDIM  256
#define KDIM  512   // K for both GEMMs (I+E = 512 for h, H = 512 for m)

// Partition: 24 column tiles (16 h-tiles cover H=512, 8 m-tiles cover E=256),
// 6 batch groups of BB=11 (groups 0..5 cover rows [g*11, g*11+11); group 5 has
// 2 dummy rows beyond B=64 whose results are computed into scratch and dropped).
#define NCOLT    24
#define NBG      6
#define NCTA     (NCOLT * NBG)     // 144 CTAs = single wave on 148 SMs
#define BB       11
#define NC       32                // cols per tile
#define RC       4                 // cols per thread (activation reuse factor)
#define NKG      32                // k-groups (threads along K)
#define KT       16                // k elements per thread (8 f32x2 weight regs/col)
#define NKG2     16                // partials after shuffle pair-reduction
#define NTHREADS 256               // 8 col-groups x 32 k-groups

typedef unsigned long long ull;

// Persistent state (double-buffered recurrence) + barrier state.
__device__ float    g_h[2][BATCH * HDIM];
__device__ float    g_m[2][BATCH * EDIM];
__device__ unsigned g_cnt = 0;
__device__ unsigned g_gen = 0;

// Packed f32x2 FMA (sm_103a; 2x FFMA throughput vs scalar 3-reg FFMA).
__device__ __forceinline__ ull ffma2(ull a, ull b, ull c) {
    ull d;
    asm("fma.rn.f32x2 %0, %1, %2, %3;" : "=l"(d) : "l"(a), "l"(b), "l"(c));
    return d;
}
__device__ __forceinline__ float2 unpack2(ull v) {
    float2 r;
    asm("mov.b64 {%0, %1}, %2;" : "=f"(r.x), "=f"(r.y) : "l"(v));
    return r;
}

// Eigen-style rational tanh, FMA-only (no MUFU): rel/abs err ~1e-6 on fp32.
// Division done with magic-seed + 3 Newton iterations (err ~1e-8).
__device__ __forceinline__ float fast_tanh(float x) {
    const float c = 7.90531110763549805f;
    x = fmaxf(-c, fminf(c, x));
    float x2 = x * x;
    float p = -2.76076847742355e-16f;
    p = fmaf(p, x2, 2.00018790482477e-13f);
    p = fmaf(p, x2, -8.60467152213735e-11f);
    p = fmaf(p, x2, 5.12229709037114e-08f);
    p = fmaf(p, x2, 1.48572235717979e-05f);
    p = fmaf(p, x2, 6.37261928875436e-04f);
    p = fmaf(p, x2, 4.89352455891786e-03f);
    p = x * p;
    float q = 1.19825839466702e-06f;
    q = fmaf(q, x2, 1.18534705686654e-04f);
    q = fmaf(q, x2, 2.26843463243900e-03f);
    q = fmaf(q, x2, 4.89352518554385e-03f);
    // reciprocal of q (q in [4.89e-3, ~1.0], always positive normal)
    float r = __uint_as_float(0x7EF311C3u - __float_as_uint(q));
    r = r * fmaf(-q, r, 2.0f);
    r = r * fmaf(-q, r, 2.0f);
    r = r * fmaf(-q, r, 2.0f);
    return p * r;
}

__global__ void __launch_bounds__(NTHREADS, 1)
rnn_persistent_kernel(const float* __restrict__ x,    // [S,B,I]
                      const float* __restrict__ h0,   // [B,H]
                      const float* __restrict__ m0,   // [B,E]
                      const float* __restrict__ We,   // [E,H]   row-major, row stride 512
                      const float* __restrict__ be,   // [E]
                      const float* __restrict__ Wih,  // [H,I+E] row-major, row stride 512
                      const float* __restrict__ bih,  // [H]
                      float* __restrict__ out,
                      int write_ht, int write_mt)
{
    __shared__ float act [BB * KDIM];        // 22528 B: staged activations [BB][512]
    __shared__ float part[BB * NKG2 * NC];   // 22528 B: k-split partials [BB][16][32]
    __shared__ float bias[NC];

    const int tid   = threadIdx.x;
    const int cg    = tid & 7;        // column group (0..7), owns RC=4 cols
    const int kg    = tid >> 3;       // k group (0..31), owns KT=16 k's
    const int tilec = blockIdx.x;     // 0..23
    const int bg    = blockIdx.y;     // 0..5
    const bool is_h = (tilec < 16);
    const int colbase = is_h ? tilec * NC : (tilec - 16) * NC;
    const int b0      = bg * BB;
    const int bvalid  = (BATCH - b0 < BB) ? (BATCH - b0) : BB;

    // Snapshot barrier generation BEFORE first arrive (safe: barrier 0 cannot
    // complete until every CTA has both snapshotted and arrived).
    unsigned gen0 = 0;
    if (tid == 0) gen0 = *(volatile unsigned*)&g_gen;

    // ---- One-time weight preload into registers (reused for all 2048 steps) ----
    // Both W_ih [512x512] and W_embed [256x512] have row stride 512 = KDIM.
    const float* Wbase = is_h ? Wih : We;
    ull w[RC][KT / 2];
    #pragma unroll
    for (int c = 0; c < RC; ++c) {
        const ulonglong2* wp = (const ulonglong2*)
            (Wbase + (size_t)(colbase + cg * RC + c) * KDIM + kg * KT);
        #pragma unroll
        for (int j2 = 0; j2 < 4; ++j2) {
            ulonglong2 v = wp[j2];
            w[c][j2 * 2]     = v.x;
            w[c][j2 * 2 + 1] = v.y;
        }
    }
    if (tid < NC) bias[tid] = is_h ? bih[colbase + tid] : be[colbase + tid];
    __syncthreads();

    for (int t = 0; t < SQ; ++t) {
        // ---- Stage activations for this CTA's batch rows into SMEM ----
        const int rbuf = (t + 1) & 1;   // buffer written at step t-1
        if (is_h) {
            // combined[b] = [ x_t[b] (256) | m_prev[b] (256) ]
            const float* msrc = (t == 0) ? m0 : g_m[rbuf];
            for (int idx = tid; idx < bvalid * 128; idx += NTHREADS) {
                int b = idx >> 7, q = idx & 127;
                float4 v;
                if (q < 64)
                    v = __ldg((const float4*)(x + ((size_t)t * BATCH + b0 + b) * IDIM) + q);
                else
                    v = __ldcg((const float4*)(msrc + (size_t)(b0 + b) * EDIM) + (q - 64));
                ((float4*)act)[b * 128 + q] = v;
            }
        } else {
            const float* hsrc = (t == 0) ? h0 : g_h[rbuf];
            for (int idx = tid; idx < bvalid * 128; idx += NTHREADS) {
                int b = idx >> 7, q = idx & 127;
                float4 v = __ldcg((const float4*)(hsrc + (size_t)(b0 + b) * HDIM) + q);
                ((float4*)act)[b * 128 + q] = v;
            }
        }
        __syncthreads();

        // ---- GEMM microkernel: register weights x SMEM activations (f32x2) ----
        #pragma unroll
        for (int b = 0; b < BB; ++b) {
            const ulonglong2* ap = (const ulonglong2*)(act + b * KDIM + kg * KT);
            ulonglong2 v0 = ap[0], v1 = ap[1], v2 = ap[2], v3 = ap[3];
            ull a[8] = { v0.x, v0.y, v1.x, v1.y, v2.x, v2.y, v3.x, v3.y };
            ull acc[RC];
            #pragma unroll
            for (int c = 0; c < RC; ++c) acc[c] = 0ull;
            #pragma unroll
            for (int j = 0; j < 8; ++j) {
                #pragma unroll
                for (int c = 0; c < RC; ++c)
                    acc[c] = ffma2(w[c][j], a[j], acc[c]);
            }
            float4 r;
            float2 f;
            f = unpack2(acc[0]); r.x = f.x + f.y;
            f = unpack2(acc[1]); r.y = f.x + f.y;
            f = unpack2(acc[2]); r.z = f.x + f.y;
            f = unpack2(acc[3]); r.w = f.x + f.y;
            // pair-reduce adjacent k-groups (lane ^ 8 flips kg bit0 within warp)
            r.x += __shfl_xor_sync(0xffffffffu, r.x, 8);
            r.y += __shfl_xor_sync(0xffffffffu, r.y, 8);
            r.z += __shfl_xor_sync(0xffffffffu, r.z, 8);
            r.w += __shfl_xor_sync(0xffffffffu, r.w, 8);
            if ((kg & 1) == 0)
                ((float4*)part)[(b * NKG2 + (kg >> 1)) * (NC / 4) + cg] = r;
        }
        __syncthreads();

        // ---- Reduce k-split partials, bias, activation, writeback ----
        const int wbuf = t & 1;
        for (int o = tid; o < bvalid * NC; o += NTHREADS) {
            int b = o >> 5, cc = o & (NC - 1);
            const float* pp = part + b * NKG2 * NC + cc;
            float s = bias[cc];
            #pragma unroll
            for (int k = 0; k < NKG2; ++k) s += pp[k * NC];
            int bglob = b0 + b;
            int col   = colbase + cc;
            if (is_h) {
                float v = fast_tanh(s);
                g_h[wbuf][bglob * HDIM + col] = v;
                out[((size_t)t * BATCH + bglob) * HDIM + col] = v;
                if (t == SQ - 1 && write_ht)
                    out[(size_t)SQ * BATCH * HDIM + (size_t)bglob * HDIM + col] = v;
            } else {
                g_m[wbuf][bglob * EDIM + col] = s;
                if (t == SQ - 1 && write_mt)
                    out[(size_t)SQ * BATCH * HDIM + (size_t)BATCH * HDIM
                        + (size_t)bglob * EDIM + col] = s;
            }
        }

        // ---- Grid barrier (sense via monotonically increasing generation) ----
        __syncthreads();
        if (tid == 0) {
            __threadfence();
            unsigned target = gen0 + (unsigned)(t + 1);
            if (atomicAdd(&g_cnt, 1u) == NCTA - 1) {
                atomicExch(&g_cnt, 0u);   // reset before releasing
                __threadfence();
                atomicAdd(&g_gen, 1u);
            } else {
                while ((int)(*(volatile unsigned*)&g_gen - target) < 0) { }
            }
            __threadfence();              // gpu-scope: invalidates this SM's L1D
        }
        __syncthreads();
    }
}

extern "C" void kernel_launch(void* const* d_in, const int* in_sizes, int n_in,
                              void* d_out, int out_size) {
    const float* x   = (const float*)d_in[0];  // input_seq [S,B,I]
    const float* h0  = (const float*)d_in[1];  // h_0 [B,H]
    const float* m0  = (const float*)d_in[2];  // m_0 [B,E]
    const float* We  = (const float*)d_in[3];  // W_embed [E,H]
    const float* be  = (const float*)d_in[4];  // b_embed [E]
    const float* Wih = (const float*)d_in[5];  // W_ih [H,I+E]
    const float* bih = (const float*)d_in[6];  // b_ih [H]
    float* out = (float*)d_out;

    // Guard tail writes against an unexpectedly smaller output buffer.
    long long seq_elems = (long long)SQ * BATCH * HDIM;
    int write_ht = (out_size >= seq_elems + (long long)BATCH * HDIM) ? 1 : 0;
    int write_mt = (out_size >= seq_elems + (long long)BATCH * HDIM
                                + (long long)BATCH * EDIM) ? 1 : 0;

    dim3 grid(NCOLT, NBG);   // 144 CTAs — single wave, all resident (148 SMs)
    dim3 block(NTHREADS);
    rnn_persistent_kernel<<<grid, block>>>(x, h0, m0, We, be, Wih, bih, out,
                                           write_ht, write_mt);
}

// round 7
// speedup vs baseline: 1.0233x; 1.0233x over previous
#include <cuda_runtime.h>

// Problem dims
#define SQ    2048
#define BATCH 64
#define IDIM  256
#define HDIM  512
#define EDIM  256
#define KDIM  512   // K for both GEMMs (I+E = 512 for h, H = 512 for m)

// Partition: 24 column tiles (16 h-tiles cover H=512, 8 m-tiles cover E=256),
// 6 batch groups of BB=11 (groups 0..5 cover rows [g*11, g*11+11); group 5 has
// 2 dummy rows beyond B=64 whose results are computed into scratch and dropped).
#define NCOLT    24
#define NBG      6
#define NCTA     (NCOLT * NBG)     // 144 CTAs = single wave on 148 SMs
#define BB       11
#define NC       32                // cols per tile
#define RC       4                 // cols per thread (activation reuse factor)
#define NKG      32                // k-groups (threads along K)
#define KT       16                // k elements per thread (8 f32x2 weight regs/col)
#define NKG2     16                // partials after shuffle pair-reduction
#define NTHREADS 256               // 8 col-groups x 32 k-groups

typedef unsigned long long ull;

// Persistent state (double-buffered recurrence) + barrier state.
__device__ float    g_h[2][BATCH * HDIM];
__device__ float    g_m[2][BATCH * EDIM];
__device__ unsigned g_cnt = 0;
__device__ unsigned g_gen = 0;

// Packed f32x2 FMA (sm_103a; 2x FFMA throughput vs scalar 3-reg FFMA).
__device__ __forceinline__ ull ffma2(ull a, ull b, ull c) {
    ull d;
    asm("fma.rn.f32x2 %0, %1, %2, %3;" : "=l"(d) : "l"(a), "l"(b), "l"(c));
    return d;
}
__device__ __forceinline__ float2 unpack2(ull v) {
    float2 r;
    asm("mov.b64 {%0, %1}, %2;" : "=f"(r.x), "=f"(r.y) : "l"(v));
    return r;
}

// Eigen-style rational tanh, FMA-only (no MUFU): rel/abs err ~1e-6 on fp32.
// Division done with magic-seed + 3 Newton iterations (err ~1e-8).
__device__ __forceinline__ float fast_tanh(float x) {
    const float c = 7.90531110763549805f;
    x = fmaxf(-c, fminf(c, x));
    float x2 = x * x;
    float p = -2.76076847742355e-16f;
    p = fmaf(p, x2, 2.00018790482477e-13f);
    p = fmaf(p, x2, -8.60467152213735e-11f);
    p = fmaf(p, x2, 5.12229709037114e-08f);
    p = fmaf(p, x2, 1.48572235717979e-05f);
    p = fmaf(p, x2, 6.37261928875436e-04f);
    p = fmaf(p, x2, 4.89352455891786e-03f);
    p = x * p;
    float q = 1.19825839466702e-06f;
    q = fmaf(q, x2, 1.18534705686654e-04f);
    q = fmaf(q, x2, 2.26843463243900e-03f);
    q = fmaf(q, x2, 4.89352518554385e-03f);
    // reciprocal of q (q in [4.89e-3, ~1.0], always positive normal)
    float r = __uint_as_float(0x7EF311C3u - __float_as_uint(q));
    r = r * fmaf(-q, r, 2.0f);
    r = r * fmaf(-q, r, 2.0f);
    r = r * fmaf(-q, r, 2.0f);
    return p * r;
}

__global__ void __launch_bounds__(NTHREADS, 1)
rnn_persistent_kernel(const float* __restrict__ x,    // [S,B,I]
                      const float* __restrict__ h0,   // [B,H]
                      const float* __restrict__ m0,   // [B,E]
                      const float* __restrict__ We,   // [E,H]   row-major, row stride 512
                      const float* __restrict__ be,   // [E]
                      const float* __restrict__ Wih,  // [H,I+E] row-major, row stride 512
                      const float* __restrict__ bih,  // [H]
                      float* __restrict__ out,
                      int write_ht, int write_mt)
{
    __shared__ float act [BB * KDIM];        // 22528 B: staged activations [BB][512]
    __shared__ float part[BB * NKG2 * NC];   // 22528 B: k-split partials [BB][16][32]
    __shared__ float bias[NC];

    const int tid   = threadIdx.x;
    const int cg    = tid & 7;        // column group (0..7), owns RC=4 cols
    const int kg    = tid >> 3;       // k group (0..31), owns KT=16 k's
    const int tilec = blockIdx.x;     // 0..23
    const int bg    = blockIdx.y;     // 0..5
    const bool is_h = (tilec < 16);
    const int colbase = is_h ? tilec * NC : (tilec - 16) * NC;
    const int b0      = bg * BB;
    const int bvalid  = (BATCH - b0 < BB) ? (BATCH - b0) : BB;

    // Snapshot barrier generation BEFORE first arrive (safe: barrier 0 cannot
    // complete until every CTA has both snapshotted and arrived).
    unsigned gen0 = 0;
    if (tid == 0) gen0 = *(volatile unsigned*)&g_gen;

    // ---- One-time weight preload into registers (reused for all 2048 steps) ----
    // Both W_ih [512x512] and W_embed [256x512] have row stride 512 = KDIM.
    const float* Wbase = is_h ? Wih : We;
    ull w[RC][KT / 2];
    #pragma unroll
    for (int c = 0; c < RC; ++c) {
        const ulonglong2* wp = (const ulonglong2*)
            (Wbase + (size_t)(colbase + cg * RC + c) * KDIM + kg * KT);
        #pragma unroll
        for (int j2 = 0; j2 < 4; ++j2) {
            ulonglong2 v = wp[j2];
            w[c][j2 * 2]     = v.x;
            w[c][j2 * 2 + 1] = v.y;
        }
    }
    if (tid < NC) bias[tid] = is_h ? bih[colbase + tid] : be[colbase + tid];
    __syncthreads();

    for (int t = 0; t < SQ; ++t) {
        // ---- Stage activations for this CTA's batch rows into SMEM ----
        const int rbuf = (t + 1) & 1;   // buffer written at step t-1
        if (is_h) {
            // combined[b] = [ x_t[b] (256) | m_prev[b] (256) ]
            const float* msrc = (t == 0) ? m0 : g_m[rbuf];
            for (int idx = tid; idx < bvalid * 128; idx += NTHREADS) {
                int b = idx >> 7, q = idx & 127;
                float4 v;
                if (q < 64)
                    v = __ldg((const float4*)(x + ((size_t)t * BATCH + b0 + b) * IDIM) + q);
                else
                    v = __ldcg((const float4*)(msrc + (size_t)(b0 + b) * EDIM) + (q - 64));
                ((float4*)act)[b * 128 + q] = v;
            }
        } else {
            const float* hsrc = (t == 0) ? h0 : g_h[rbuf];
            for (int idx = tid; idx < bvalid * 128; idx += NTHREADS) {
                int b = idx >> 7, q = idx & 127;
                float4 v = __ldcg((const float4*)(hsrc + (size_t)(b0 + b) * HDIM) + q);
                ((float4*)act)[b * 128 + q] = v;
            }
        }
        __syncthreads();

        // ---- GEMM microkernel: register weights x SMEM activations (f32x2) ----
        #pragma unroll
        for (int b = 0; b < BB; ++b) {
            const ulonglong2* ap = (const ulonglong2*)(act + b * KDIM + kg * KT);
            ulonglong2 v0 = ap[0], v1 = ap[1], v2 = ap[2], v3 = ap[3];
            ull a[8] = { v0.x, v0.y, v1.x, v1.y, v2.x, v2.y, v3.x, v3.y };
            ull acc[RC];
            #pragma unroll
            for (int c = 0; c < RC; ++c) acc[c] = 0ull;
            #pragma unroll
            for (int j = 0; j < 8; ++j) {
                #pragma unroll
                for (int c = 0; c < RC; ++c)
                    acc[c] = ffma2(w[c][j], a[j], acc[c]);
            }
            float4 r;
            float2 f;
            f = unpack2(acc[0]); r.x = f.x + f.y;
            f = unpack2(acc[1]); r.y = f.x + f.y;
            f = unpack2(acc[2]); r.z = f.x + f.y;
            f = unpack2(acc[3]); r.w = f.x + f.y;
            // pair-reduce adjacent k-groups (lane ^ 8 flips kg bit0 within warp)
            r.x += __shfl_xor_sync(0xffffffffu, r.x, 8);
            r.y += __shfl_xor_sync(0xffffffffu, r.y, 8);
            r.z += __shfl_xor_sync(0xffffffffu, r.z, 8);
            r.w += __shfl_xor_sync(0xffffffffu, r.w, 8);
            if ((kg & 1) == 0)
                ((float4*)part)[(b * NKG2 + (kg >> 1)) * (NC / 4) + cg] = r;
        }
        __syncthreads();

        // ---- Reduce k-split partials, bias, activation, writeback ----
        const int wbuf = t & 1;
        for (int o = tid; o < bvalid * NC; o += NTHREADS) {
            int b = o >> 5, cc = o & (NC - 1);
            const float* pp = part + b * NKG2 * NC + cc;
            float s = bias[cc];
            #pragma unroll
            for (int k = 0; k < NKG2; ++k) s += pp[k * NC];
            int bglob = b0 + b;
            int col   = colbase + cc;
            if (is_h) {
                float v = fast_tanh(s);
                g_h[wbuf][bglob * HDIM + col] = v;
                out[((size_t)t * BATCH + bglob) * HDIM + col] = v;
                if (t == SQ - 1 && write_ht)
                    out[(size_t)SQ * BATCH * HDIM + (size_t)bglob * HDIM + col] = v;
            } else {
                g_m[wbuf][bglob * EDIM + col] = s;
                if (t == SQ - 1 && write_mt)
                    out[(size_t)SQ * BATCH * HDIM + (size_t)BATCH * HDIM
                        + (size_t)bglob * EDIM + col] = s;
            }
        }

        // ---- Grid barrier (sense via monotonically increasing generation) ----
        __syncthreads();
        if (tid == 0) {
            __threadfence();
            unsigned target = gen0 + (unsigned)(t + 1);
            if (atomicAdd(&g_cnt, 1u) == NCTA - 1) {
                atomicExch(&g_cnt, 0u);   // reset before releasing
                __threadfence();
                atomicAdd(&g_gen, 1u);
            } else {
                while ((int)(*(volatile unsigned*)&g_gen - target) < 0) { }
            }
            __threadfence();              // gpu-scope: invalidates this SM's L1D
        }
        __syncthreads();
    }
}

extern "C" void kernel_launch(void* const* d_in, const int* in_sizes, int n_in,
                              void* d_out, int out_size) {
    const float* x   = (const float*)d_in[0];  // input_seq [S,B,I]
    const float* h0  = (const float*)d_in[1];  // h_0 [B,H]
    const float* m0  = (const float*)d_in[2];  // m_0 [B,E]
    const float* We  = (const float*)d_in[3];  // W_embed [E,H]
    const float* be  = (const float*)d_in[4];  // b_embed [E]
    const float* Wih = (const float*)d_in[5];  // W_ih [H,I+E]
    const float* bih = (const float*)d_in[6];  // b_ih [H]
    float* out = (float*)d_out;

    // Guard tail writes against an unexpectedly smaller output buffer.
    long long seq_elems = (long long)SQ * BATCH * HDIM;
    int write_ht = (out_size >= seq_elems + (long long)BATCH * HDIM) ? 1 : 0;
    int write_mt = (out_size >= seq_elems + (long long)BATCH * HDIM
                                + (long long)BATCH * EDIM) ? 1 : 0;

    dim3 grid(NCOLT, NBG);   // 144 CTAs — single wave, all resident (148 SMs)
    dim3 block(NTHREADS);
    rnn_persistent_kernel<<<grid, block>>>(x, h0, m0, We, be, Wih, bih, out,
                                           write_ht, write_mt);
}

// round 8
// speedup vs baseline: 1.4664x; 1.4330x over previous
#include <cuda_runtime.h>

#define SQ    2048
#define BATCH 64
#define IDIM  256
#define HDIM  512
#define EDIM  256
#define BH    (BATCH * HDIM)    // 32768 floats per timestep

typedef unsigned long long ull;

// Persistent scratch (1MB + 2KB) as __device__ globals (no allocs allowed).
__device__ float g_Whh[HDIM * HDIM];   // W_hh[i][j] = sum_e Wm[i][e] * We[e][j]
__device__ float g_c[HDIM];            // c[i] = sum_e Wm[i][e] * be[e]

// Packed f32x2 FMA (sm_103a): 2x MACs per issue vs scalar FFMA.
__device__ __forceinline__ ull ffma2(ull a, ull b, ull c) {
    ull d;
    asm("fma.rn.f32x2 %0, %1, %2, %3;" : "=l"(d) : "l"(a), "l"(b), "l"(c));
    return d;
}
__device__ __forceinline__ float2 unpack2(ull v) {
    float2 r;
    asm("mov.b64 {%0, %1}, %2;" : "=f"(r.x), "=f"(r.y) : "l"(v));
    return r;
}

// FMA-only rational tanh (no MUFU), abs err ~1e-6 (validated R5: rel 6.4e-7).
__device__ __forceinline__ float fast_tanh(float x) {
    const float c = 7.90531110763549805f;
    x = fmaxf(-c, fminf(c, x));
    float x2 = x * x;
    float p = -2.76076847742355e-16f;
    p = fmaf(p, x2, 2.00018790482477e-13f);
    p = fmaf(p, x2, -8.60467152213735e-11f);
    p = fmaf(p, x2, 5.12229709037114e-08f);
    p = fmaf(p, x2, 1.48572235717979e-05f);
    p = fmaf(p, x2, 6.37261928875436e-04f);
    p = fmaf(p, x2, 4.89352455891786e-03f);
    p = x * p;
    float q = 1.19825839466702e-06f;
    q = fmaf(q, x2, 1.18534705686654e-04f);
    q = fmaf(q, x2, 2.26843463243900e-03f);
    q = fmaf(q, x2, 4.89352518554385e-03f);
    float r = __uint_as_float(0x7EF311C3u - __float_as_uint(q));
    r = r * fmaf(-q, r, 2.0f);
    r = r * fmaf(-q, r, 2.0f);
    r = r * fmaf(-q, r, 2.0f);
    return p * r;
}

// ---------------------------------------------------------------------------
// Kernel 0: W_hh = Wm @ We  (Wm = Wih[:,256:512]) and c = Wm @ be.
// ---------------------------------------------------------------------------
__global__ void prep_whh_kernel(const float* __restrict__ Wih,
                                const float* __restrict__ We,
                                const float* __restrict__ be) {
    int i = blockIdx.x, tid = threadIdx.x;
    const float* wm = Wih + (size_t)i * 512 + IDIM;   // Wm row i (256 wide)
    float4 acc = make_float4(0.f, 0.f, 0.f, 0.f);
    float cacc = 0.f;
    #pragma unroll 4
    for (int e = 0; e < EDIM; ++e) {
        float a  = __ldg(wm + e);
        float4 b = __ldg((const float4*)(We + (size_t)e * HDIM) + tid);
        acc.x = fmaf(a, b.x, acc.x);
        acc.y = fmaf(a, b.y, acc.y);
        acc.z = fmaf(a, b.z, acc.z);
        acc.w = fmaf(a, b.w, acc.w);
        cacc  = fmaf(a, __ldg(be + e), cacc);
    }
    ((float4*)(g_Whh + (size_t)i * 512))[tid] = acc;
    if (tid == 0) g_c[i] = cacc;
}

// ---------------------------------------------------------------------------
// Kernel 1: stage U[t] into out[t]:
//   t>0 : U = x_t @ Wx^T + b_ih + c
//   t==0: U = x_0 @ Wx^T + m_0 @ Wm^T + b_ih   (full pre-activation)
// CTA tile: 32 rows x 64 cols, K=256 per pass.
// 256 thr = 16 colg (RC=4) x 16 kg (KT=16). grid=(16, 2048).
// dyn smem: act 32*256 + part 8*8*64 = 12288 floats = 49152 B (= default cap).
// ---------------------------------------------------------------------------
__global__ void __launch_bounds__(256, 2)
precompute_u_kernel(const float* __restrict__ x,
                    const float* __restrict__ m0,
                    const float* __restrict__ Wih,
                    const float* __restrict__ bih,
                    float* __restrict__ out) {
    extern __shared__ float sm1[];
    float* act  = sm1;                 // [32][256]
    float* part = sm1 + 32 * 256;      // [8 rows][8 ksets][64 cols]

    const int tid = threadIdx.x;
    const int cg  = tid & 15;
    const int kg  = tid >> 4;
    const int t   = blockIdx.y;
    const int colt = blockIdx.x & 7, rowg = blockIdx.x >> 3;
    const int colbase = colt * 64, rowbase = rowg * 32;

    float sreg[8];
    #pragma unroll
    for (int i = 0; i < 8; ++i) sreg[i] = 0.f;

    const int npass = (t == 0) ? 2 : 1;
    for (int pass = 0; pass < npass; ++pass) {
        // weights: pass0 = Wx (k in [0,256)), pass1 = Wm (k in [256,512))
        ull w[4][8];
        const int koff = pass ? IDIM : 0;
        #pragma unroll
        for (int c = 0; c < 4; ++c) {
            const ulonglong2* wp = (const ulonglong2*)
                (Wih + (size_t)(colbase + cg * 4 + c) * 512 + koff + kg * 16);
            #pragma unroll
            for (int j2 = 0; j2 < 4; ++j2) {
                ulonglong2 v = wp[j2];
                w[c][2 * j2]     = v.x;
                w[c][2 * j2 + 1] = v.y;
            }
        }
        const float* src = pass ? (m0 + (size_t)rowbase * EDIM)
                                : (x + ((size_t)t * BATCH + rowbase) * IDIM);
        __syncthreads();
        #pragma unroll
        for (int i = 0; i < 8; ++i)
            ((float4*)act)[tid + i * 256] = __ldg((const float4*)src + tid + i * 256);
        __syncthreads();

        for (int chunk = 0; chunk < 4; ++chunk) {
            #pragma unroll
            for (int b = 0; b < 8; ++b) {
                const ulonglong2* ap =
                    (const ulonglong2*)(act + (chunk * 8 + b) * 256 + kg * 16);
                ull acc[4] = {0ull, 0ull, 0ull, 0ull};
                #pragma unroll
                for (int j2 = 0; j2 < 4; ++j2) {
                    ulonglong2 v = ap[j2];
                    #pragma unroll
                    for (int c = 0; c < 4; ++c) {
                        acc[c] = ffma2(w[c][2 * j2],     v.x, acc[c]);
                        acc[c] = ffma2(w[c][2 * j2 + 1], v.y, acc[c]);
                    }
                }
                float4 r; float2 f;
                f = unpack2(acc[0]); r.x = f.x + f.y;
                f = unpack2(acc[1]); r.y = f.x + f.y;
                f = unpack2(acc[2]); r.z = f.x + f.y;
                f = unpack2(acc[3]); r.w = f.x + f.y;
                r.x += __shfl_xor_sync(0xffffffffu, r.x, 16);
                r.y += __shfl_xor_sync(0xffffffffu, r.y, 16);
                r.z += __shfl_xor_sync(0xffffffffu, r.z, 16);
                r.w += __shfl_xor_sync(0xffffffffu, r.w, 16);
                if (!(kg & 1))
                    ((float4*)part)[(b * 8 + (kg >> 1)) * 16 + cg] = r;
            }
            __syncthreads();
            #pragma unroll
            for (int h = 0; h < 2; ++h) {
                int o = tid + h * 256;
                int r = o >> 6, cc = o & 63;
                float s = 0.f;
                #pragma unroll
                for (int k = 0; k < 8; ++k) s += part[(r * 8 + k) * 64 + cc];
                sreg[chunk * 2 + h] += s;
            }
            __syncthreads();
        }
    }
    #pragma unroll
    for (int chunk = 0; chunk < 4; ++chunk) {
        #pragma unroll
        for (int h = 0; h < 2; ++h) {
            int o = tid + h * 256;
            int r = o >> 6, cc = o & 63;
            int col = colbase + cc;
            float bias = __ldg(bih + col) + ((t > 0) ? g_c[col] : 0.f);
            out[(size_t)t * BH + (size_t)(rowbase + chunk * 8 + r) * HDIM + col]
                = sreg[chunk * 2 + h] + bias;
        }
    }
}

// ---------------------------------------------------------------------------
// Kernel 2: sequential recurrence, 1024 supersteps.
//   H[t] = tanh(U[t] + H[t-2] @ W_hh^T),  H[-1]=h_0, H[0]=tanh(U[0]) directly.
// 16 independent 8-CTA clusters: cluster = (parity, batch-group-of-8).
// CTA: 8 rows x 64 cols, K=512. 256 thr = 16 colg (RC=4) x 16 kg (KT=32).
// H[t] overwrites U[t] in-place in `out`. Sync = barrier.cluster (rel/acq),
// with next-U prefetch issued in the arrive->wait gap.
// ---------------------------------------------------------------------------
__global__ void __launch_bounds__(256, 1) __cluster_dims__(8, 1, 1)
rnn_seq_kernel(const float* __restrict__ h0, float* __restrict__ out) {
    __shared__ float act [8 * 512];        // 16KB
    __shared__ float part[8 * 8 * 64];     // 16KB

    const int tid = threadIdx.x;
    const int cg  = tid & 15;
    const int kg  = tid >> 4;
    const int colt = blockIdx.x;           // 0..7 = cluster rank
    const int grp  = blockIdx.y;           // 0..15
    const int p    = grp >> 3;             // parity
    const int b0   = (grp & 7) * 8;        // batch base
    const int colbase = colt * 64;

    // W_hh slice into registers: 4 cols x 32 k = 64 ull, reused 1024x.
    ull w[4][16];
    #pragma unroll
    for (int c = 0; c < 4; ++c) {
        const ulonglong2* wp = (const ulonglong2*)
            (g_Whh + (size_t)(colbase + cg * 4 + c) * 512 + kg * 32);
        #pragma unroll
        for (int j2 = 0; j2 < 8; ++j2) {
            ulonglong2 v = wp[j2];
            w[c][2 * j2]     = v.x;
            w[c][2 * j2 + 1] = v.y;
        }
    }

    const int o0 = tid, o1 = tid + 256;
    const int r0 = o0 >> 6, c0 = o0 & 63, r1 = o1 >> 6, c1 = o1 & 63;
    const size_t a0 = (size_t)(b0 + r0) * HDIM + colbase + c0;
    const size_t a1 = (size_t)(b0 + r1) * HDIM + colbase + c1;

    int t = p;
    float u0 = out[(size_t)t * BH + a0];   // prefetch U[t]
    float u1 = out[(size_t)t * BH + a1];

    for (int s = 0; s < 1024; ++s, t += 2) {
        const bool do_gemm = (s > 0) || (p == 1);
        if (do_gemm) {
            // stage H[t-2] (8 rows x 512) — peers wrote it last superstep (L2)
            const float* src = (s == 0) ? (h0 + (size_t)b0 * HDIM)
                                        : (out + (size_t)(t - 2) * BH + (size_t)b0 * HDIM);
            #pragma unroll
            for (int i = 0; i < 4; ++i)
                ((float4*)act)[tid + i * 256] =
                    __ldcg((const float4*)src + tid + i * 256);
            __syncthreads();

            #pragma unroll
            for (int b = 0; b < 8; ++b) {
                const ulonglong2* ap = (const ulonglong2*)(act + b * 512 + kg * 32);
                ull acc[4] = {0ull, 0ull, 0ull, 0ull};
                #pragma unroll
                for (int j2 = 0; j2 < 8; ++j2) {
                    ulonglong2 v = ap[j2];
                    #pragma unroll
                    for (int c = 0; c < 4; ++c) {
                        acc[c] = ffma2(w[c][2 * j2],     v.x, acc[c]);
                        acc[c] = ffma2(w[c][2 * j2 + 1], v.y, acc[c]);
                    }
                }
                float4 r; float2 f;
                f = unpack2(acc[0]); r.x = f.x + f.y;
                f = unpack2(acc[1]); r.y = f.x + f.y;
                f = unpack2(acc[2]); r.z = f.x + f.y;
                f = unpack2(acc[3]); r.w = f.x + f.y;
                r.x += __shfl_xor_sync(0xffffffffu, r.x, 16);
                r.y += __shfl_xor_sync(0xffffffffu, r.y, 16);
                r.z += __shfl_xor_sync(0xffffffffu, r.z, 16);
                r.w += __shfl_xor_sync(0xffffffffu, r.w, 16);
                if (!(kg & 1))
                    ((float4*)part)[(b * 8 + (kg >> 1)) * 16 + cg] = r;
            }
            __syncthreads();
        }

        float s0 = u0, s1 = u1;
        if (do_gemm) {
            #pragma unroll
            for (int k = 0; k < 8; ++k) {
                s0 += part[(r0 * 8 + k) * 64 + c0];
                s1 += part[(r1 * 8 + k) * 64 + c1];
            }
        }
        float* dst = out + (size_t)t * BH;
        dst[a0] = fast_tanh(s0);
        dst[a1] = fast_tanh(s1);

        asm volatile("barrier.cluster.arrive.aligned;" ::: "memory");
        if (s < 1023) {                    // prefetch U[t+2] in the barrier gap
            u0 = out[(size_t)(t + 2) * BH + a0];
            u1 = out[(size_t)(t + 2) * BH + a1];
        }
        asm volatile("barrier.cluster.wait.aligned;" ::: "memory");
        __syncthreads();   // ensure part/act reuse ordering across supersteps
    }
}

// ---------------------------------------------------------------------------
// Kernel 3: tails.  h_T = H[2047] (copy), m_T = H[2046] @ We^T + be.
// ---------------------------------------------------------------------------
__global__ void finalize_kernel(const float* __restrict__ We,
                                const float* __restrict__ be,
                                float* __restrict__ out,
                                int write_ht, int write_mt) {
    __shared__ float hrow[HDIM];
    const int b = blockIdx.x, tid = threadIdx.x;
    const float* h2046 = out + (size_t)(SQ - 2) * BH + (size_t)b * HDIM;
    hrow[tid]       = h2046[tid];
    hrow[tid + 256] = h2046[tid + 256];
    if (write_ht) {
        const float* h2047 = out + (size_t)(SQ - 1) * BH + (size_t)b * HDIM;
        float* d = out + (size_t)SQ * BH + (size_t)b * HDIM;
        d[tid]       = h2047[tid];
        d[tid + 256] = h2047[tid + 256];
    }
    __syncthreads();
    if (write_mt && tid < EDIM) {
        float acc = be[tid];
        const float4* wr = (const float4*)(We + (size_t)tid * HDIM);
        #pragma unroll 4
        for (int j4 = 0; j4 < 128; ++j4) {
            float4 wv = __ldg(wr + j4);
            const float* hp = hrow + j4 * 4;
            acc = fmaf(wv.x, hp[0], acc);
            acc = fmaf(wv.y, hp[1], acc);
            acc = fmaf(wv.z, hp[2], acc);
            acc = fmaf(wv.w, hp[3], acc);
        }
        out[(size_t)SQ * BH + (size_t)BATCH * HDIM + (size_t)b * EDIM + tid] = acc;
    }
}

extern "C" void kernel_launch(void* const* d_in, const int* in_sizes, int n_in,
                              void* d_out, int out_size) {
    const float* x   = (const float*)d_in[0];  // input_seq [S,B,I]
    const float* h0  = (const float*)d_in[1];  // h_0 [B,H]
    const float* m0  = (const float*)d_in[2];  // m_0 [B,E]
    const float* We  = (const float*)d_in[3];  // W_embed [E,H]
    const float* be  = (const float*)d_in[4];  // b_embed [E]
    const float* Wih = (const float*)d_in[5];  // W_ih [H,I+E]
    const float* bih = (const float*)d_in[6];  // b_ih [H]
    float* out = (float*)d_out;

    long long seq_elems = (long long)SQ * BH;
    int write_ht = (out_size >= seq_elems + (long long)BATCH * HDIM) ? 1 : 0;
    int write_mt = (out_size >= seq_elems + (long long)BATCH * HDIM
                                + (long long)BATCH * EDIM) ? 1 : 0;

    // 0) W_hh = Wm @ We, c = Wm @ be
    prep_whh_kernel<<<HDIM, 128>>>(Wih, We, be);
    // 1) U[t] -> out[t] for all t (fully parallel); 49152 B = default dyn-smem cap
    precompute_u_kernel<<<dim3(16, SQ), 256, 49152>>>(x, m0, Wih, bih, out);
    // 2) sequential recurrence: 16 independent 8-CTA clusters, 1024 supersteps
    rnn_seq_kernel<<<dim3(8, 16), 256>>>(h0, out);
    // 3) tails
    finalize_kernel<<<BATCH, 256>>>(We, be, out, write_ht, write_mt);
}